// round 1
// baseline (speedup 1.0000x reference)
#include <cuda_runtime.h>

// GraphDecoder (NRI decoder) fused fp32 kernels for sm_103a.
// Uses packed fma.rn.f32x2 to double fp32 FMA throughput.

#define BB 32
#define NN 64
#define FF 128
#define KK 4
#define EE 4032          // N*(N-1)
#define XSTR 260         // padded row stride for 256-wide smem tiles
#define AUGSTR 388       // padded row stride for 384-wide tile
#define P1STR 260

// scratch: aggregated messages [B, N, 256] (2 MB, static device global)
__device__ float g_agg[BB * NN * 256];

// ---------- packed f32x2 helpers ----------
__device__ __forceinline__ unsigned long long pack2(float x) {
    unsigned long long r;
    asm("mov.b64 %0, {%1, %1};" : "=l"(r) : "f"(x));
    return r;
}
__device__ __forceinline__ unsigned long long packab(float a, float b) {
    unsigned long long r;
    asm("mov.b64 %0, {%1, %2};" : "=l"(r) : "f"(a), "f"(b));
    return r;
}
__device__ __forceinline__ void unpack2(unsigned long long v, float& a, float& b) {
    asm("mov.b64 {%0, %1}, %2;" : "=f"(a), "=f"(b) : "l"(v));
}
__device__ __forceinline__ unsigned long long fma2(unsigned long long a,
                                                   unsigned long long b,
                                                   unsigned long long c) {
    unsigned long long d;
    asm("fma.rn.f32x2 %0, %1, %2, %3;" : "=l"(d) : "l"(a), "l"(b), "l"(c));
    return d;
}

// =====================================================================
// Kernel 1: per-edge 2-layer MLP over K edge types, fused with gather,
// rel_type weighting and receiver-node aggregation.
// Block = (node n, batch b). 63 real edges + 1 dummy row. 256 threads.
// Micro-tile: 8 edges x 8 cols per thread (as 4 f32x2 pairs).
// =====================================================================
__global__ void __launch_bounds__(256, 1)
edge_mlp_kernel(const float* __restrict__ inputs,
                const float* __restrict__ rel_type,
                const float* __restrict__ W1, const float* __restrict__ b1,
                const float* __restrict__ W2, const float* __restrict__ b2,
                float* __restrict__ agg)
{
    extern __shared__ float sm[];
    float* Xs  = sm;                    // [64][XSTR]  pre_msg (recv|send)
    float* Hs  = Xs + 64 * XSTR;        // [64][XSTR]  layer-1 activations
    float* Wc  = Hs + 64 * XSTR;        // [32][256]   streamed weight chunk
    float* rts = Wc + 32 * 256;         // [64][4]     rel_type tile

    const int n   = blockIdx.x;
    const int b   = blockIdx.y;
    const int tid = threadIdx.x;
    const int cg  = tid & 31;           // column group 0..31
    const int er  = tid >> 5;           // edge-row group 0..7
    const int col0 = cg << 3;

    // ---- gather X: row le -> edge e = 63n + le (le<63), row 63 dummy 0 ----
    const float* inb = inputs + (size_t)b * NN * FF;
    for (int idx = tid; idx < 64 * 64; idx += 256) {
        int le = idx >> 6, c4 = idx & 63;
        float4 v = make_float4(0.f, 0.f, 0.f, 0.f);
        if (le < 63) {
            if (c4 < 32) {
                v = *(const float4*)(inb + n * FF + (c4 << 2));            // receiver
            } else {
                int j = le + (le >= n);                                     // sender
                v = *(const float4*)(inb + j * FF + ((c4 - 32) << 2));
            }
        }
        *(float4*)(Xs + le * XSTR + (c4 << 2)) = v;
    }
    {
        int le = tid >> 2, k = tid & 3;
        rts[tid] = (le < 63) ? rel_type[((size_t)b * EE + n * 63 + le) * KK + k] : 0.f;
    }

    float aggp[8];
#pragma unroll
    for (int j = 0; j < 8; ++j) aggp[j] = 0.f;

#pragma unroll 1
    for (int k = 0; k < KK; ++k) {
        const float* W1k = W1 + k * 65536;
        const float* W2k = W2 + k * 65536;

        // hb = b1 + recvFeat @ W1[0:128]  (edge-independent half of layer 1)
        unsigned long long hb[4];
        {
            float4 t0 = *(const float4*)(b1 + k * 256 + col0);
            float4 t1 = *(const float4*)(b1 + k * 256 + col0 + 4);
            hb[0] = packab(t0.x, t0.y); hb[1] = packab(t0.z, t0.w);
            hb[2] = packab(t1.x, t1.y); hb[3] = packab(t1.z, t1.w);
        }
#pragma unroll 1
        for (int fc = 0; fc < 4; ++fc) {
            __syncthreads();
            const float* wsrc = W1k + fc * 32 * 256;
            for (int idx = tid; idx < 32 * 64; idx += 256)
                *(float4*)(Wc + ((idx >> 6) << 8) + ((idx & 63) << 2)) =
                    *(const float4*)(wsrc + ((idx >> 6) << 8) + ((idx & 63) << 2));
            __syncthreads();
#pragma unroll 8
            for (int f = 0; f < 32; ++f) {
                unsigned long long xp = pack2(Xs[fc * 32 + f]);   // row 0 recv feats
                const float* wrow = Wc + (f << 8) + col0;
                ulonglong2 wA = *(const ulonglong2*)(wrow);
                ulonglong2 wB = *(const ulonglong2*)(wrow + 4);
                hb[0] = fma2(xp, wA.x, hb[0]); hb[1] = fma2(xp, wA.y, hb[1]);
                hb[2] = fma2(xp, wB.x, hb[2]); hb[3] = fma2(xp, wB.y, hb[3]);
            }
        }

        // per-edge sender half of layer 1
        unsigned long long acc[8][4];
#pragma unroll
        for (int i = 0; i < 8; ++i) {
            acc[i][0] = hb[0]; acc[i][1] = hb[1]; acc[i][2] = hb[2]; acc[i][3] = hb[3];
        }
#pragma unroll 1
        for (int fc = 4; fc < 8; ++fc) {
            __syncthreads();
            const float* wsrc = W1k + fc * 32 * 256;
            for (int idx = tid; idx < 32 * 64; idx += 256)
                *(float4*)(Wc + ((idx >> 6) << 8) + ((idx & 63) << 2)) =
                    *(const float4*)(wsrc + ((idx >> 6) << 8) + ((idx & 63) << 2));
            __syncthreads();
#pragma unroll 8
            for (int f = 0; f < 32; ++f) {
                const float* wrow = Wc + (f << 8) + col0;
                ulonglong2 wA = *(const ulonglong2*)(wrow);
                ulonglong2 wB = *(const ulonglong2*)(wrow + 4);
#pragma unroll
                for (int i = 0; i < 8; ++i) {
                    unsigned long long xp = pack2(Xs[(er * 8 + i) * XSTR + fc * 32 + f]);
                    acc[i][0] = fma2(xp, wA.x, acc[i][0]);
                    acc[i][1] = fma2(xp, wA.y, acc[i][1]);
                    acc[i][2] = fma2(xp, wB.x, acc[i][2]);
                    acc[i][3] = fma2(xp, wB.y, acc[i][3]);
                }
            }
        }

        // relu -> Hs
#pragma unroll
        for (int i = 0; i < 8; ++i) {
            float4 v0, v1;
            unpack2(acc[i][0], v0.x, v0.y); unpack2(acc[i][1], v0.z, v0.w);
            unpack2(acc[i][2], v1.x, v1.y); unpack2(acc[i][3], v1.z, v1.w);
            v0.x = fmaxf(v0.x, 0.f); v0.y = fmaxf(v0.y, 0.f);
            v0.z = fmaxf(v0.z, 0.f); v0.w = fmaxf(v0.w, 0.f);
            v1.x = fmaxf(v1.x, 0.f); v1.y = fmaxf(v1.y, 0.f);
            v1.z = fmaxf(v1.z, 0.f); v1.w = fmaxf(v1.w, 0.f);
            *(float4*)(Hs + (er * 8 + i) * XSTR + col0)     = v0;
            *(float4*)(Hs + (er * 8 + i) * XSTR + col0 + 4) = v1;
        }

        // layer 2
        unsigned long long a2[8][4];
        {
            float4 t0 = *(const float4*)(b2 + k * 256 + col0);
            float4 t1 = *(const float4*)(b2 + k * 256 + col0 + 4);
            unsigned long long c0 = packab(t0.x, t0.y), c1 = packab(t0.z, t0.w);
            unsigned long long c2 = packab(t1.x, t1.y), c3 = packab(t1.z, t1.w);
#pragma unroll
            for (int i = 0; i < 8; ++i) {
                a2[i][0] = c0; a2[i][1] = c1; a2[i][2] = c2; a2[i][3] = c3;
            }
        }
#pragma unroll 1
        for (int fc = 0; fc < 8; ++fc) {
            __syncthreads();   // also guarantees Hs writes visible on fc==0
            const float* wsrc = W2k + fc * 32 * 256;
            for (int idx = tid; idx < 32 * 64; idx += 256)
                *(float4*)(Wc + ((idx >> 6) << 8) + ((idx & 63) << 2)) =
                    *(const float4*)(wsrc + ((idx >> 6) << 8) + ((idx & 63) << 2));
            __syncthreads();
#pragma unroll 8
            for (int f = 0; f < 32; ++f) {
                const float* wrow = Wc + (f << 8) + col0;
                ulonglong2 wA = *(const ulonglong2*)(wrow);
                ulonglong2 wB = *(const ulonglong2*)(wrow + 4);
#pragma unroll
                for (int i = 0; i < 8; ++i) {
                    unsigned long long xp = pack2(Hs[(er * 8 + i) * XSTR + fc * 32 + f]);
                    a2[i][0] = fma2(xp, wA.x, a2[i][0]);
                    a2[i][1] = fma2(xp, wA.y, a2[i][1]);
                    a2[i][2] = fma2(xp, wB.x, a2[i][2]);
                    a2[i][3] = fma2(xp, wB.y, a2[i][3]);
                }
            }
        }

        // relu, rel_type weighting, accumulate node aggregation
#pragma unroll
        for (int i = 0; i < 8; ++i) {
            float w = rts[(er * 8 + i) * 4 + k];
            float x0, x1;
            unpack2(a2[i][0], x0, x1); aggp[0] += w * fmaxf(x0, 0.f); aggp[1] += w * fmaxf(x1, 0.f);
            unpack2(a2[i][1], x0, x1); aggp[2] += w * fmaxf(x0, 0.f); aggp[3] += w * fmaxf(x1, 0.f);
            unpack2(a2[i][2], x0, x1); aggp[4] += w * fmaxf(x0, 0.f); aggp[5] += w * fmaxf(x1, 0.f);
            unpack2(a2[i][3], x0, x1); aggp[6] += w * fmaxf(x0, 0.f); aggp[7] += w * fmaxf(x1, 0.f);
        }
    }

    // reduce aggp over the 8 edge-row groups (reuse Wc as scratch)
    __syncthreads();
#pragma unroll
    for (int j = 0; j < 8; ++j) Wc[(er << 8) + col0 + j] = aggp[j];
    __syncthreads();
    {
        float s = 0.f;
#pragma unroll
        for (int r = 0; r < 8; ++r) s += Wc[(r << 8) + tid];
        agg[((size_t)b * NN + n) * 256 + tid] = s;
    }
}

// =====================================================================
// Kernel 2: output MLP 384->256->256->128 + residual.
// Block = (half of nodes, batch b): 32 rows, 128 threads, 8x8 micro-tiles.
// =====================================================================
__global__ void __launch_bounds__(128, 1)
out_mlp_kernel(const float* __restrict__ inputs, const float* __restrict__ agg,
               const float* __restrict__ Wo1, const float* __restrict__ bo1,
               const float* __restrict__ Wo2, const float* __restrict__ bo2,
               const float* __restrict__ Wo3, const float* __restrict__ bo3,
               float* __restrict__ out)
{
    extern __shared__ float sm[];
    float* augS = sm;                     // [32][AUGSTR] aug, later reused for p2
    float* p1S  = augS + 32 * AUGSTR;     // [32][P1STR]
    float* Wc   = p1S + 32 * P1STR;       // [32][256]

    const int half = blockIdx.x;
    const int b    = blockIdx.y;
    const int r0   = half * 32;
    const int tid  = threadIdx.x;
    const int cg   = tid & 31;
    const int er   = tid >> 5;            // 0..3
    const int col0 = cg << 3;

    // load aug = [inputs | agg]
    for (int idx = tid; idx < 32 * 96; idx += 128) {
        int r = idx / 96, c4 = idx % 96;
        float4 v;
        if (c4 < 32)
            v = *(const float4*)(inputs + ((size_t)(b * NN) + r0 + r) * FF + (c4 << 2));
        else
            v = *(const float4*)(agg + ((size_t)(b * NN) + r0 + r) * 256 + ((c4 - 32) << 2));
        *(float4*)(augS + r * AUGSTR + (c4 << 2)) = v;
    }

    // ---- layer 1: 384 -> 256 ----
    unsigned long long acc[8][4];
    {
        float4 t0 = *(const float4*)(bo1 + col0);
        float4 t1 = *(const float4*)(bo1 + col0 + 4);
        unsigned long long c0 = packab(t0.x, t0.y), c1 = packab(t0.z, t0.w);
        unsigned long long c2 = packab(t1.x, t1.y), c3 = packab(t1.z, t1.w);
#pragma unroll
        for (int i = 0; i < 8; ++i) {
            acc[i][0] = c0; acc[i][1] = c1; acc[i][2] = c2; acc[i][3] = c3;
        }
    }
#pragma unroll 1
    for (int fc = 0; fc < 12; ++fc) {
        __syncthreads();
        const float* wsrc = Wo1 + fc * 32 * 256;
        for (int idx = tid; idx < 32 * 64; idx += 128)
            *(float4*)(Wc + ((idx >> 6) << 8) + ((idx & 63) << 2)) =
                *(const float4*)(wsrc + ((idx >> 6) << 8) + ((idx & 63) << 2));
        __syncthreads();
#pragma unroll 8
        for (int f = 0; f < 32; ++f) {
            const float* wrow = Wc + (f << 8) + col0;
            ulonglong2 wA = *(const ulonglong2*)(wrow);
            ulonglong2 wB = *(const ulonglong2*)(wrow + 4);
#pragma unroll
            for (int i = 0; i < 8; ++i) {
                unsigned long long xp = pack2(augS[(er * 8 + i) * AUGSTR + fc * 32 + f]);
                acc[i][0] = fma2(xp, wA.x, acc[i][0]);
                acc[i][1] = fma2(xp, wA.y, acc[i][1]);
                acc[i][2] = fma2(xp, wB.x, acc[i][2]);
                acc[i][3] = fma2(xp, wB.y, acc[i][3]);
            }
        }
    }
#pragma unroll
    for (int i = 0; i < 8; ++i) {
        float4 v0, v1;
        unpack2(acc[i][0], v0.x, v0.y); unpack2(acc[i][1], v0.z, v0.w);
        unpack2(acc[i][2], v1.x, v1.y); unpack2(acc[i][3], v1.z, v1.w);
        v0.x = fmaxf(v0.x, 0.f); v0.y = fmaxf(v0.y, 0.f);
        v0.z = fmaxf(v0.z, 0.f); v0.w = fmaxf(v0.w, 0.f);
        v1.x = fmaxf(v1.x, 0.f); v1.y = fmaxf(v1.y, 0.f);
        v1.z = fmaxf(v1.z, 0.f); v1.w = fmaxf(v1.w, 0.f);
        *(float4*)(p1S + (er * 8 + i) * P1STR + col0)     = v0;
        *(float4*)(p1S + (er * 8 + i) * P1STR + col0 + 4) = v1;
    }

    // ---- layer 2: 256 -> 256 (output relu -> augS reused as p2) ----
    {
        float4 t0 = *(const float4*)(bo2 + col0);
        float4 t1 = *(const float4*)(bo2 + col0 + 4);
        unsigned long long c0 = packab(t0.x, t0.y), c1 = packab(t0.z, t0.w);
        unsigned long long c2 = packab(t1.x, t1.y), c3 = packab(t1.z, t1.w);
#pragma unroll
        for (int i = 0; i < 8; ++i) {
            acc[i][0] = c0; acc[i][1] = c1; acc[i][2] = c2; acc[i][3] = c3;
        }
    }
#pragma unroll 1
    for (int fc = 0; fc < 8; ++fc) {
        __syncthreads();   // also guarantees p1S writes visible on fc==0
        const float* wsrc = Wo2 + fc * 32 * 256;
        for (int idx = tid; idx < 32 * 64; idx += 128)
            *(float4*)(Wc + ((idx >> 6) << 8) + ((idx & 63) << 2)) =
                *(const float4*)(wsrc + ((idx >> 6) << 8) + ((idx & 63) << 2));
        __syncthreads();
#pragma unroll 8
        for (int f = 0; f < 32; ++f) {
            const float* wrow = Wc + (f << 8) + col0;
            ulonglong2 wA = *(const ulonglong2*)(wrow);
            ulonglong2 wB = *(const ulonglong2*)(wrow + 4);
#pragma unroll
            for (int i = 0; i < 8; ++i) {
                unsigned long long xp = pack2(p1S[(er * 8 + i) * P1STR + fc * 32 + f]);
                acc[i][0] = fma2(xp, wA.x, acc[i][0]);
                acc[i][1] = fma2(xp, wA.y, acc[i][1]);
                acc[i][2] = fma2(xp, wB.x, acc[i][2]);
                acc[i][3] = fma2(xp, wB.y, acc[i][3]);
            }
        }
    }
    __syncthreads();   // all augS (layer-1 input) reads done before overwrite
#pragma unroll
    for (int i = 0; i < 8; ++i) {
        float4 v0, v1;
        unpack2(acc[i][0], v0.x, v0.y); unpack2(acc[i][1], v0.z, v0.w);
        unpack2(acc[i][2], v1.x, v1.y); unpack2(acc[i][3], v1.z, v1.w);
        v0.x = fmaxf(v0.x, 0.f); v0.y = fmaxf(v0.y, 0.f);
        v0.z = fmaxf(v0.z, 0.f); v0.w = fmaxf(v0.w, 0.f);
        v1.x = fmaxf(v1.x, 0.f); v1.y = fmaxf(v1.y, 0.f);
        v1.z = fmaxf(v1.z, 0.f); v1.w = fmaxf(v1.w, 0.f);
        *(float4*)(augS + (er * 8 + i) * AUGSTR + col0)     = v0;
        *(float4*)(augS + (er * 8 + i) * AUGSTR + col0 + 4) = v1;
    }

    // ---- layer 3: 256 -> 128, + residual ----
    unsigned long long a3[8][2];
    {
        float4 tb = *(const float4*)(bo3 + (cg << 2));
        unsigned long long c0 = packab(tb.x, tb.y), c1 = packab(tb.z, tb.w);
#pragma unroll
        for (int i = 0; i < 8; ++i) { a3[i][0] = c0; a3[i][1] = c1; }
    }
#pragma unroll 1
    for (int fc = 0; fc < 8; ++fc) {
        __syncthreads();   // p2 writes visible on fc==0
        const float* wsrc = Wo3 + fc * 32 * 128;
        for (int idx = tid; idx < 32 * 32; idx += 128)
            *(float4*)(Wc + ((idx >> 5) << 7) + ((idx & 31) << 2)) =
                *(const float4*)(wsrc + ((idx >> 5) << 7) + ((idx & 31) << 2));
        __syncthreads();
#pragma unroll 8
        for (int f = 0; f < 32; ++f) {
            const float* wrow = Wc + (f << 7) + (cg << 2);
            ulonglong2 wA = *(const ulonglong2*)(wrow);
#pragma unroll
            for (int i = 0; i < 8; ++i) {
                unsigned long long xp = pack2(augS[(er * 8 + i) * AUGSTR + fc * 32 + f]);
                a3[i][0] = fma2(xp, wA.x, a3[i][0]);
                a3[i][1] = fma2(xp, wA.y, a3[i][1]);
            }
        }
    }
#pragma unroll
    for (int i = 0; i < 8; ++i) {
        int r = r0 + er * 8 + i;
        float4 res = *(const float4*)(inputs + ((size_t)(b * NN) + r) * FF + (cg << 2));
        float x0, x1;
        unpack2(a3[i][0], x0, x1); res.x += x0; res.y += x1;
        unpack2(a3[i][1], x0, x1); res.z += x0; res.w += x1;
        *(float4*)(out + ((size_t)(b * NN) + r) * FF + (cg << 2)) = res;
    }
}

// =====================================================================
extern "C" void kernel_launch(void* const* d_in, const int* in_sizes, int n_in,
                              void* d_out, int out_size)
{
    const float* inputs   = (const float*)d_in[0];
    const float* rel_type = (const float*)d_in[1];
    // d_in[2] rel_rec, d_in[3] rel_send: analytic, unused
    const float* W1  = (const float*)d_in[4];
    const float* b1  = (const float*)d_in[5];
    const float* W2  = (const float*)d_in[6];
    const float* b2  = (const float*)d_in[7];
    const float* Wo1 = (const float*)d_in[8];
    const float* bo1 = (const float*)d_in[9];
    const float* Wo2 = (const float*)d_in[10];
    const float* bo2 = (const float*)d_in[11];
    const float* Wo3 = (const float*)d_in[12];
    const float* bo3 = (const float*)d_in[13];
    float* out = (float*)d_out;

    float* agg;
    cudaGetSymbolAddress((void**)&agg, g_agg);

    const int smemA = (64 * XSTR * 2 + 32 * 256 + 256) * 4;           // 166,912 B
    const int smemB = (32 * AUGSTR + 32 * P1STR + 32 * 256) * 4;      // 115,712 B
    cudaFuncSetAttribute(edge_mlp_kernel, cudaFuncAttributeMaxDynamicSharedMemorySize, smemA);
    cudaFuncSetAttribute(out_mlp_kernel, cudaFuncAttributeMaxDynamicSharedMemorySize, smemB);

    edge_mlp_kernel<<<dim3(NN, BB), 256, smemA>>>(inputs, rel_type, W1, b1, W2, b2, agg);
    out_mlp_kernel<<<dim3(2, BB), 128, smemB>>>(inputs, agg, Wo1, bo1, Wo2, bo2, Wo3, bo3, out);
}